// round 6
// baseline (speedup 1.0000x reference)
#include <cuda_runtime.h>
#include <cuda_fp16.h>
#include <cstdint>
#include <cstddef>

#define NR 2048
#define NC 32
#define NO 32
#define NI 32
#define NB 64
#define NCO (NC*NO)      // 1024
#define NCHUNK 64        // route chunks of 32
#define TILE 2048        // 32 o x 64 b per (c, chunk) partial

// Scratch (device globals: allocation-free contract)
__device__ __half g_W16[(size_t)NC * NR * NO * NI];  // [c][r][o][i] 134 MB
__device__ __half g_xF[(size_t)NR * 8 * 32 * 8];     // [r][nt][lane][8] 8 MB
__device__ float  g_spart[(size_t)NC * NCHUNK * TILE]; // 16 MB partial s
__device__ float  g_blog[NR * NC];                   // routing logits b_ij [r][c]
__device__ float  g_cij[NR * NC];                    // softmax(b_ij) over r
__device__ float  g_v2[NCO * NB];                    // v in [c][o][b] layout

// D += A*B (m16n8k16, fp16 in, fp32 acc) — plain mma.sync
__device__ __forceinline__ void mma16816(float* c, const uint32_t* a,
                                         uint32_t b0, uint32_t b1) {
    asm volatile(
        "mma.sync.aligned.m16n8k16.row.col.f32.f16.f16.f32 "
        "{%0,%1,%2,%3},{%4,%5,%6,%7},{%8,%9},{%0,%1,%2,%3};"
        : "+f"(c[0]), "+f"(c[1]), "+f"(c[2]), "+f"(c[3])
        : "r"(a[0]), "r"(a[1]), "r"(a[2]), "r"(a[3]), "r"(b0), "r"(b1));
}

// ---------------------------------------------------------------------------
__global__ void k_zero() {
    int i = blockIdx.x * blockDim.x + threadIdx.x;
    if (i < NR * NC) g_blog[i] = 0.f;
}

// ---------------------------------------------------------------------------
// Convert W fp32 [r][c][o][i] -> fp16 [c][r][o][i]. Block per (r,c) tile.
__global__ void __launch_bounds__(256) k_conv_w(const float* __restrict__ W) {
    const size_t blk = blockIdx.x;           // r*32 + c
    const size_t r = blk >> 5, c = blk & 31;
    const float4 v = ((const float4*)(W + (r * NC + c) * 1024))[threadIdx.x];
    uint2 o;
    *(__half2*)&o.x = __floats2half2_rn(v.x, v.y);
    *(__half2*)&o.y = __floats2half2_rn(v.z, v.w);
    ((uint2*)(g_W16 + (c * NR + r) * 1024))[threadIdx.x] = o;
}

// ---------------------------------------------------------------------------
// Convert x fp32 [b][r][i] -> fragment-packed fp16 g_xF[r][nt][lane][8]:
// h[ks*4+reg*2+e] = x16(b = nt*8 + (lane>>2), i = ks*16 + 2*(lane&3) + reg*8 + e)
__global__ void __launch_bounds__(256) k_conv_x(const float* __restrict__ x) {
    const int r = blockIdx.x;
    const int t = threadIdx.x;
    const int nt = t >> 5, lane = t & 31;
    const int g = lane >> 2, tg = lane & 3;
    const float* xb = x + ((size_t)(nt * 8 + g) * NR + r) * NI;
    uint4 o;
    uint32_t h[4];
#pragma unroll
    for (int ks = 0; ks < 2; ++ks)
#pragma unroll
        for (int reg = 0; reg < 2; ++reg) {
            const int i = ks * 16 + 2 * tg + reg * 8;
            *(__half2*)&h[ks * 2 + reg] = __floats2half2_rn(xb[i], xb[i + 1]);
        }
    o.x = h[0]; o.y = h[1]; o.z = h[2]; o.w = h[3];
    *(uint4*)(g_xF + ((size_t)r * 8 + nt) * 256 + lane * 8) = o;
}

// ---------------------------------------------------------------------------
// c_ij[:, c] = softmax over r of b_ij[:, c]. One block per capsule c.
__global__ void __launch_bounds__(256) k_softmax() {
    const int c   = blockIdx.x;
    const int tid = threadIdx.x;
    __shared__ float sm[8];

    float vals[8];
#pragma unroll
    for (int j = 0; j < 8; ++j) vals[j] = g_blog[(tid + j * 256) * NC + c];

    float m = vals[0];
#pragma unroll
    for (int j = 1; j < 8; ++j) m = fmaxf(m, vals[j]);
#pragma unroll
    for (int off = 16; off; off >>= 1) m = fmaxf(m, __shfl_xor_sync(0xffffffffu, m, off));
    if ((tid & 31) == 0) sm[tid >> 5] = m;
    __syncthreads();
    float mm = sm[0];
#pragma unroll
    for (int j = 1; j < 8; ++j) mm = fmaxf(mm, sm[j]);
    __syncthreads();

    float e[8];
    float s = 0.f;
#pragma unroll
    for (int j = 0; j < 8; ++j) { e[j] = expf(vals[j] - mm); s += e[j]; }
#pragma unroll
    for (int off = 16; off; off >>= 1) s += __shfl_xor_sync(0xffffffffu, s, off);
    if ((tid & 31) == 0) sm[tid >> 5] = s;
    __syncthreads();
    float tot = 0.f;
#pragma unroll
    for (int j = 0; j < 8; ++j) tot += sm[j];
    const float inv = 1.f / tot;
#pragma unroll
    for (int j = 0; j < 8; ++j) g_cij[(tid + j * 256) * NC + c] = e[j] * inv;
}

// ---------------------------------------------------------------------------
// Load A fragments for route r, capsule c, m-tile mt (W16 [c][r][o][i]).
// a[ks][j]: o = mt*16 + g + (j&1)*8, i = ks*16 + 2*tg + ((j>>1)&1)*8
__device__ __forceinline__ void load_A(uint32_t A[2][4], int c, int r,
                                       int mt, int g, int tg) {
    const __half* wp = g_W16 + ((size_t)c * NR + r) * 1024 + mt * 16 * 32;
#pragma unroll
    for (int ks = 0; ks < 2; ++ks)
#pragma unroll
        for (int j = 0; j < 4; ++j) {
            const int o = g + (j & 1) * 8;
            const int i = ks * 16 + 2 * tg + ((j >> 1) & 1) * 8;
            A[ks][j] = *(const uint32_t*)(wp + o * 32 + i);
        }
}

// ---------------------------------------------------------------------------
// s partial: block (chunk, c) covers routes [chunk*32, +32). Warp w: mt=w&1,
// rgroup=w>>1 handles 8 routes. Accumulate c_ij-scaled per-route MMA tiles
// (fp32 rescale) into registers; cross-rgroup reduce in smem; write partial.
__global__ void __launch_bounds__(256) k_s() {
    const int chunk = blockIdx.x, c = blockIdx.y;
    const int tid = threadIdx.x, w = tid >> 5, lane = tid & 31;
    const int g = lane >> 2, tg = lane & 3;
    const int mt = w & 1, rg = w >> 1;
    __shared__ float red_s[3][TILE];

    float acc[8][4];
#pragma unroll
    for (int nt = 0; nt < 8; ++nt)
#pragma unroll
        for (int j = 0; j < 4; ++j) acc[nt][j] = 0.f;

#pragma unroll 2
    for (int it = 0; it < 8; ++it) {
        const int r = chunk * 32 + rg * 8 + it;
        const float cr = g_cij[r * NC + c];
        uint32_t A[2][4];
        load_A(A, c, r, mt, g, tg);
        const uint4* xp = (const uint4*)(g_xF + (size_t)r * 2048) + lane;
#pragma unroll
        for (int nt = 0; nt < 8; ++nt) {
            const uint4 bx = xp[nt * 32];
            float t4[4] = {0.f, 0.f, 0.f, 0.f};
            mma16816(t4, A[0], bx.x, bx.y);
            mma16816(t4, A[1], bx.z, bx.w);
#pragma unroll
            for (int j = 0; j < 4; ++j) acc[nt][j] = fmaf(cr, t4[j], acc[nt][j]);
        }
    }

    // cross-rgroup reduction
    if (rg > 0) {
#pragma unroll
        for (int nt = 0; nt < 8; ++nt)
#pragma unroll
            for (int j = 0; j < 4; ++j) {
                const int idx = (mt * 16 + g + ((j >> 1) & 1) * 8) * 64
                              + nt * 8 + 2 * tg + (j & 1);
                red_s[rg - 1][idx] = acc[nt][j];
            }
    }
    __syncthreads();
    if (rg == 0) {
        float* dst = g_spart + ((size_t)c * NCHUNK + chunk) * TILE;
#pragma unroll
        for (int nt = 0; nt < 8; ++nt)
#pragma unroll
            for (int j = 0; j < 4; ++j) {
                const int idx = (mt * 16 + g + ((j >> 1) & 1) * 8) * 64
                              + nt * 8 + 2 * tg + (j & 1);
                dst[idx] = acc[nt][j] + red_s[0][idx] + red_s[1][idx] + red_s[2][idx];
            }
    }
}

// ---------------------------------------------------------------------------
// Reduce partials over chunks, squash -> g_v2 (+ final output on last iter).
__global__ void __launch_bounds__(256) k_red(float* __restrict__ outp) {
    const int idx = blockIdx.x * 256 + threadIdx.x;   // 65536 = c*2048 + e
    const int c = idx >> 11, e = idx & 2047;
    const float* p = g_spart + (size_t)c * NCHUNK * TILE + e;
    float s = 0.f;
#pragma unroll 8
    for (int k = 0; k < NCHUNK; ++k) s += p[(size_t)k * TILE];
    const float sq = s * s;
    const float v  = sq * s / ((1.f + sq) * sqrtf(sq));
    g_v2[c * TILE + e] = v;
    if (outp) {
        const int o = e >> 6, b = e & 63;
        outp[b * NCO + c * NO + o] = v;
    }
}

// ---------------------------------------------------------------------------
// a-pass: b_ij[r,c] += (1/B) * sum_{o,b} u_hat[r,c,o,b] * v[c,o,b],
// with u_hat recomputed by MMA. Block (chunk, c); same warp layout as k_s.
__global__ void __launch_bounds__(256) k_a() {
    const int chunk = blockIdx.x, c = blockIdx.y;
    const int tid = threadIdx.x, w = tid >> 5, lane = tid & 31;
    const int g = lane >> 2, tg = lane & 3;
    const int mt = w & 1, rg = w >> 1;
    __shared__ float a_sm[32];

    if (tid < 32) a_sm[tid] = 0.f;
    __syncthreads();

    // register-resident v at this thread's accumulator positions
    float vv[8][4];
#pragma unroll
    for (int nt = 0; nt < 8; ++nt)
#pragma unroll
        for (int j = 0; j < 4; ++j)
            vv[nt][j] = g_v2[c * TILE + (mt * 16 + g + ((j >> 1) & 1) * 8) * 64
                             + nt * 8 + 2 * tg + (j & 1)];

#pragma unroll 2
    for (int it = 0; it < 8; ++it) {
        const int rl = rg * 8 + it;
        const int r = chunk * 32 + rl;
        uint32_t A[2][4];
        load_A(A, c, r, mt, g, tg);
        const uint4* xp = (const uint4*)(g_xF + (size_t)r * 2048) + lane;
        float pa = 0.f;
#pragma unroll
        for (int nt = 0; nt < 8; ++nt) {
            const uint4 bx = xp[nt * 32];
            float t4[4] = {0.f, 0.f, 0.f, 0.f};
            mma16816(t4, A[0], bx.x, bx.y);
            mma16816(t4, A[1], bx.z, bx.w);
            pa = fmaf(t4[0], vv[nt][0], pa);
            pa = fmaf(t4[1], vv[nt][1], pa);
            pa = fmaf(t4[2], vv[nt][2], pa);
            pa = fmaf(t4[3], vv[nt][3], pa);
        }
#pragma unroll
        for (int off = 16; off; off >>= 1) pa += __shfl_xor_sync(0xffffffffu, pa, off);
        if (lane == 0) atomicAdd(&a_sm[rl], pa);
    }
    __syncthreads();
    if (tid < 32)
        g_blog[(chunk * 32 + tid) * NC + c] += a_sm[tid] * (1.f / NB);
}

// ---------------------------------------------------------------------------
extern "C" void kernel_launch(void* const* d_in, const int* in_sizes, int n_in,
                              void* d_out, int out_size) {
    const float* x = (const float*)d_in[0];  // [B, R, I]
    const float* W = (const float*)d_in[1];  // [R, C, O, I]
    if (n_in >= 2 && in_sizes[0] > in_sizes[1]) {  // robust to input ordering
        const float* t = x; x = W; W = t;
    }
    float* out = (float*)d_out;

    k_zero<<<64, 1024>>>();
    k_conv_w<<<NR * NC, 256>>>(W);
    k_conv_x<<<NR, 256>>>(x);
    for (int it = 0; it < 3; ++it) {
        k_softmax<<<NC, 256>>>();
        k_s<<<dim3(NCHUNK, NC), 256>>>();
        k_red<<<256, 256>>>(it == 2 ? out : nullptr);
        if (it < 2) k_a<<<dim3(NCHUNK, NC), 256>>>();
    }
}

// round 7
// speedup vs baseline: 1.1558x; 1.1558x over previous
#include <cuda_runtime.h>
#include <cuda_fp16.h>
#include <cstdint>
#include <cstddef>

#define NR 2048
#define NC 32
#define NO 32
#define NI 32
#define NB 64
#define NCO (NC*NO)        // 1024
#define RSTRIDE (NCO*NB)   // 65536 elements per route in u_hat

// Scratch (device globals: allocation-free contract)
__device__ __half g_uhat[(size_t)NR * NCO * NB]; // [r][c][o][b]  268 MB fp16
__device__ float  g_spart[512 * 2 * 128];        // k_s partials [co2][half][128]
__device__ float  g_blog[NR * NC];               // routing logits b_ij [r][c]
__device__ float  g_cij[NR * NC];                // softmax(b_ij) over r
__device__ float  g_v2[NCO * NB];                // v in [c][o][b] layout

// ---------------------------------------------------------------------------
// pack two fp32 -> f16x2 (low = a, high = b)
__device__ __forceinline__ uint32_t pack_f16x2(float a, float b) {
    uint32_t r;
    asm("cvt.rn.f16x2.f32 %0, %1, %2;" : "=r"(r) : "f"(b), "f"(a));
    return r;
}
// D += A*B (m16n8k16, fp16 in, fp32 acc) — plain mma.sync
__device__ __forceinline__ void mma16816(float* c, const uint32_t* a,
                                         uint32_t b0, uint32_t b1) {
    asm volatile(
        "mma.sync.aligned.m16n8k16.row.col.f32.f16.f16.f32 "
        "{%0,%1,%2,%3},{%4,%5,%6,%7},{%8,%9},{%0,%1,%2,%3};"
        : "+f"(c[0]), "+f"(c[1]), "+f"(c[2]), "+f"(c[3])
        : "r"(a[0]), "r"(a[1]), "r"(a[2]), "r"(a[3]), "r"(b0), "r"(b1));
}

// ---------------------------------------------------------------------------
__global__ void k_zero() {
    int i = blockIdx.x * blockDim.x + threadIdx.x;
    if (i < NR * NC) g_blog[i] = 0.f;
}

// ---------------------------------------------------------------------------
// u_hat via mma.sync (single fp16 MMA — R6 showed pure-fp16 error ~3.6e-4 ok):
// per route r, D[1024co x 64b] = W_r[1024x32] @ x_r^T.
// Block = route r, 8 warps; warp w owns co rows [w*128, +128) (8 m16 tiles).
__global__ void __launch_bounds__(256) k_uhat(const float* __restrict__ x,
                                              const float* __restrict__ W) {
    const int r    = blockIdx.x;
    const int tid  = threadIdx.x;
    const int w    = tid >> 5;
    const int lane = tid & 31;
    const int g    = lane >> 2;   // group id 0..7
    const int tg   = lane & 3;    // thread-in-group

    // B fragments (x_r as k16 x n8 col-major): B[nt][ks][reg]
    uint32_t B[8][2][2];
#pragma unroll
    for (int nt = 0; nt < 8; ++nt) {
        const float* xr = x + (size_t)(nt * 8 + g) * (NR * NI) + (size_t)r * NI;
#pragma unroll
        for (int ks = 0; ks < 2; ++ks) {
            const float2 v0 = *(const float2*)(xr + ks * 16 + 2 * tg);
            const float2 v1 = *(const float2*)(xr + ks * 16 + 2 * tg + 8);
            B[nt][ks][0] = pack_f16x2(v0.x, v0.y);
            B[nt][ks][1] = pack_f16x2(v1.x, v1.y);
        }
    }

    const float* wbase = W + (size_t)r * (NCO * NI);
    __half* const ubase = g_uhat + (size_t)r * RSTRIDE;

#pragma unroll 1
    for (int mt = 0; mt < 8; ++mt) {
        const int co0 = w * 128 + mt * 16 + g;      // rows g and g+8 of tile
        const float* wr0 = wbase + (size_t)co0 * NI;
        const float* wr1 = wr0 + 8 * NI;

        uint32_t A[2][4];
#pragma unroll
        for (int ks = 0; ks < 2; ++ks) {
            float2 v;
            v = *(const float2*)(wr0 + ks * 16 + 2 * tg);     A[ks][0] = pack_f16x2(v.x, v.y);
            v = *(const float2*)(wr1 + ks * 16 + 2 * tg);     A[ks][1] = pack_f16x2(v.x, v.y);
            v = *(const float2*)(wr0 + ks * 16 + 2 * tg + 8); A[ks][2] = pack_f16x2(v.x, v.y);
            v = *(const float2*)(wr1 + ks * 16 + 2 * tg + 8); A[ks][3] = pack_f16x2(v.x, v.y);
        }

#pragma unroll
        for (int nt = 0; nt < 8; ++nt) {
            float acc[4] = {0.f, 0.f, 0.f, 0.f};
            mma16816(acc, A[0], B[nt][0][0], B[nt][0][1]);
            mma16816(acc, A[1], B[nt][1][0], B[nt][1][1]);
            const int b0 = nt * 8 + 2 * tg;
            *(__half2*)(ubase + (size_t)co0 * NB + b0) =
                __floats2half2_rn(acc[0], acc[1]);
            *(__half2*)(ubase + (size_t)(co0 + 8) * NB + b0) =
                __floats2half2_rn(acc[2], acc[3]);
        }
    }
}

// ---------------------------------------------------------------------------
// c_ij[:, c] = softmax over r of b_ij[:, c]. One block per capsule c.
__global__ void __launch_bounds__(256) k_softmax() {
    const int c   = blockIdx.x;
    const int tid = threadIdx.x;
    __shared__ float sm[8];

    float vals[8];
#pragma unroll
    for (int j = 0; j < 8; ++j) vals[j] = g_blog[(tid + j * 256) * NC + c];

    float m = vals[0];
#pragma unroll
    for (int j = 1; j < 8; ++j) m = fmaxf(m, vals[j]);
#pragma unroll
    for (int off = 16; off; off >>= 1) m = fmaxf(m, __shfl_xor_sync(0xffffffffu, m, off));
    if ((tid & 31) == 0) sm[tid >> 5] = m;
    __syncthreads();
    float mm = sm[0];
#pragma unroll
    for (int j = 1; j < 8; ++j) mm = fmaxf(mm, sm[j]);
    __syncthreads();

    float e[8];
    float s = 0.f;
#pragma unroll
    for (int j = 0; j < 8; ++j) { e[j] = expf(vals[j] - mm); s += e[j]; }
#pragma unroll
    for (int off = 16; off; off >>= 1) s += __shfl_xor_sync(0xffffffffu, s, off);
    if ((tid & 31) == 0) sm[tid >> 5] = s;
    __syncthreads();
    float tot = 0.f;
#pragma unroll
    for (int j = 0; j < 8; ++j) tot += sm[j];
    const float inv = 1.f / tot;
#pragma unroll
    for (int j = 0; j < 8; ++j) g_cij[(tid + j * 256) * NC + c] = e[j] * inv;
}

// ---------------------------------------------------------------------------
// s partial: block (co2, half) covers routes [half*1024, +1024).
// warp = seg of 128 routes; lane: co_l = lane>>4, b-quad = (lane&15)*4.
// Writes 128 partial sums to g_spart.
__global__ void __launch_bounds__(256) k_s() {
    const int co2  = blockIdx.x;          // 0..511 (co pair)
    const int half = blockIdx.y;          // 0..1 (route half)
    const int c    = co2 >> 4;
    const int tid  = threadIdx.x;
    __shared__ float cs[1024];
    __shared__ float red[8][128];

#pragma unroll
    for (int j = 0; j < 4; ++j)
        cs[tid + j * 256] = g_cij[(half * 1024 + tid + j * 256) * NC + c];
    __syncthreads();

    const int seg  = tid >> 5;
    const int lane = tid & 31;
    const int co_l = lane >> 4;
    const int b4   = (lane & 15) * 4;
    const int r0   = half * 1024 + seg * 128;
    const uint2* p = (const uint2*)(g_uhat + (size_t)r0 * RSTRIDE
                                    + (size_t)co2 * 128 + co_l * 64 + b4);
    const float* csp = cs + seg * 128;

    float a0 = 0.f, a1 = 0.f, a2 = 0.f, a3 = 0.f;
#pragma unroll 8
    for (int k = 0; k < 128; ++k) {
        const uint2 u = p[(size_t)k * (RSTRIDE / 4)];
        const float2 f0 = __half22float2(*(const __half2*)&u.x);
        const float2 f1 = __half22float2(*(const __half2*)&u.y);
        const float cc = csp[k];
        a0 = fmaf(cc, f0.x, a0);
        a1 = fmaf(cc, f0.y, a1);
        a2 = fmaf(cc, f1.x, a2);
        a3 = fmaf(cc, f1.y, a3);
    }
    red[seg][co_l * 64 + b4 + 0] = a0;
    red[seg][co_l * 64 + b4 + 1] = a1;
    red[seg][co_l * 64 + b4 + 2] = a2;
    red[seg][co_l * 64 + b4 + 3] = a3;
    __syncthreads();

    if (tid < 128) {
        float s = 0.f;
#pragma unroll
        for (int j = 0; j < 8; ++j) s += red[j][tid];
        g_spart[(co2 * 2 + half) * 128 + tid] = s;
    }
}

// ---------------------------------------------------------------------------
// Combine halves, squash -> g_v2 (+ final output on last iter). 65536 lanes.
__global__ void __launch_bounds__(256) k_red(float* __restrict__ outp) {
    const int idx = blockIdx.x * 256 + threadIdx.x;   // co2*128 + e  (65536)
    const int co2 = idx >> 7, e = idx & 127;
    const float s = g_spart[(co2 * 2) * 128 + e] + g_spart[(co2 * 2 + 1) * 128 + e];
    const int co = co2 * 2 + (e >> 6);
    const int b  = e & 63;
    const float sq = s * s;
    const float v  = sq * s / ((1.f + sq) * sqrtf(sq));
    g_v2[co * NB + b] = v;                 // [c][o][b] for the a-pass
    if (outp) outp[b * NCO + co] = v;      // [b][c][o][1] final output
}

// ---------------------------------------------------------------------------
// b_ij[r,c] += (1/B) * sum_{b,o} u_hat[r][c][o][b] * v[c][o][b].
__global__ void __launch_bounds__(256) k_a() {
    const int c    = blockIdx.y;
    const int r0   = blockIdx.x * 32;
    const int tid  = threadIdx.x;
    const int lane = tid & 31;
    const int w    = tid >> 5;
    __shared__ __align__(16) float vsm[NO * NB];  // 8 KB

    const float4* vsrc = (const float4*)(g_v2 + c * (NO * NB));
    float4* vdst = (float4*)vsm;
#pragma unroll
    for (int j = 0; j < 2; ++j) vdst[tid + j * 256] = vsrc[tid + j * 256];
    __syncthreads();

    float4 vr[16];
#pragma unroll
    for (int k = 0; k < 8; ++k) {
        vr[2 * k]     = ((const float4*)vsm)[2 * (lane + k * 32)];
        vr[2 * k + 1] = ((const float4*)vsm)[2 * (lane + k * 32) + 1];
    }

#pragma unroll
    for (int i = 0; i < 4; ++i) {
        const int r = r0 + w * 4 + i;
        const uint4* up = (const uint4*)(g_uhat + (size_t)r * RSTRIDE + c * (NO * NB));
        float p = 0.f;
#pragma unroll
        for (int k = 0; k < 8; ++k) {
            const uint4 u = up[lane + k * 32];
            const float2 f0 = __half22float2(*(const __half2*)&u.x);
            const float2 f1 = __half22float2(*(const __half2*)&u.y);
            const float2 f2 = __half22float2(*(const __half2*)&u.z);
            const float2 f3 = __half22float2(*(const __half2*)&u.w);
            const float4 v0 = vr[2 * k];
            const float4 v1 = vr[2 * k + 1];
            p = fmaf(f0.x, v0.x, p); p = fmaf(f0.y, v0.y, p);
            p = fmaf(f1.x, v0.z, p); p = fmaf(f1.y, v0.w, p);
            p = fmaf(f2.x, v1.x, p); p = fmaf(f2.y, v1.y, p);
            p = fmaf(f3.x, v1.z, p); p = fmaf(f3.y, v1.w, p);
        }
#pragma unroll
        for (int off = 16; off; off >>= 1) p += __shfl_xor_sync(0xffffffffu, p, off);
        if (lane == 0) g_blog[r * NC + c] += p * (1.f / NB);
    }
}

// ---------------------------------------------------------------------------
extern "C" void kernel_launch(void* const* d_in, const int* in_sizes, int n_in,
                              void* d_out, int out_size) {
    const float* x = (const float*)d_in[0];  // [B, R, I]
    const float* W = (const float*)d_in[1];  // [R, C, O, I]
    if (n_in >= 2 && in_sizes[0] > in_sizes[1]) {  // robust to input ordering
        const float* t = x; x = W; W = t;
    }
    float* out = (float*)d_out;

    k_zero<<<64, 1024>>>();
    k_uhat<<<NR, 256>>>(x, W);
    for (int it = 0; it < 3; ++it) {
        k_softmax<<<NC, 256>>>();
        k_s<<<dim3(512, 2), 256>>>();
        k_red<<<256, 256>>>(it == 2 ? out : nullptr);
        if (it < 2) k_a<<<dim3(64, 32), 256>>>();
    }
}

// round 8
// speedup vs baseline: 1.2340x; 1.0677x over previous
#include <cuda_runtime.h>
#include <cuda_fp16.h>
#include <cstdint>
#include <cstddef>

#define NR 2048
#define NC 32
#define NO 32
#define NI 32
#define NB 64
#define NCO (NC*NO)        // 1024
#define RSTRIDE (NCO*NB)   // 65536 elements per route in u_hat
#define C_UNI (1.0f/2048.0f)

// Scratch (device globals: allocation-free contract)
__device__ __half g_uhat[(size_t)NR * NCO * NB]; // [r][c][o][b]  268 MB fp16
__device__ float  g_spart[512 * 4 * 128];        // k_s partials [co2][q][128]
__device__ float  g_blog[NC * NR];               // routing logits b_ij [c][r]
__device__ float  g_cij[NC * NR];                // softmax(b) over r, [c][r]
__device__ float  g_v2[NCO * NB];                // v in [c][o][b] layout

// ---------------------------------------------------------------------------
__device__ __forceinline__ uint32_t pack_f16x2(float a, float b) {
    uint32_t r;
    asm("cvt.rn.f16x2.f32 %0, %1, %2;" : "=r"(r) : "f"(b), "f"(a));
    return r;
}
// D += A*B (m16n8k16, fp16 in, fp32 acc) — plain mma.sync
__device__ __forceinline__ void mma16816(float* c, const uint32_t* a,
                                         uint32_t b0, uint32_t b1) {
    asm volatile(
        "mma.sync.aligned.m16n8k16.row.col.f32.f16.f16.f32 "
        "{%0,%1,%2,%3},{%4,%5,%6,%7},{%8,%9},{%0,%1,%2,%3};"
        : "+f"(c[0]), "+f"(c[1]), "+f"(c[2]), "+f"(c[3])
        : "r"(a[0]), "r"(a[1]), "r"(a[2]), "r"(a[3]), "r"(b0), "r"(b1));
}

// ---------------------------------------------------------------------------
// u_hat via mma.sync: per route r, D[1024co x 64b] = W_r[1024x32] @ x_r^T.
// Block = route r, 8 warps; warp w owns co rows [w*128, +128) (8 m16 tiles).
__global__ void __launch_bounds__(256) k_uhat(const float* __restrict__ x,
                                              const float* __restrict__ W) {
    const int r    = blockIdx.x;
    const int tid  = threadIdx.x;
    const int w    = tid >> 5;
    const int lane = tid & 31;
    const int g    = lane >> 2;   // group id 0..7
    const int tg   = lane & 3;    // thread-in-group

    // B fragments (x_r as k16 x n8 col-major): B[nt][ks][reg]
    uint32_t B[8][2][2];
#pragma unroll
    for (int nt = 0; nt < 8; ++nt) {
        const float* xr = x + (size_t)(nt * 8 + g) * (NR * NI) + (size_t)r * NI;
#pragma unroll
        for (int ks = 0; ks < 2; ++ks) {
            const float2 v0 = *(const float2*)(xr + ks * 16 + 2 * tg);
            const float2 v1 = *(const float2*)(xr + ks * 16 + 2 * tg + 8);
            B[nt][ks][0] = pack_f16x2(v0.x, v0.y);
            B[nt][ks][1] = pack_f16x2(v1.x, v1.y);
        }
    }

    const float* wbase = W + (size_t)r * (NCO * NI);
    __half* const ubase = g_uhat + (size_t)r * RSTRIDE;

#pragma unroll 1
    for (int mt = 0; mt < 8; ++mt) {
        const int co0 = w * 128 + mt * 16 + g;      // rows g and g+8 of tile
        const float* wr0 = wbase + (size_t)co0 * NI;
        const float* wr1 = wr0 + 8 * NI;

        uint32_t A[2][4];
#pragma unroll
        for (int ks = 0; ks < 2; ++ks) {
            float2 v;
            v = *(const float2*)(wr0 + ks * 16 + 2 * tg);     A[ks][0] = pack_f16x2(v.x, v.y);
            v = *(const float2*)(wr1 + ks * 16 + 2 * tg);     A[ks][1] = pack_f16x2(v.x, v.y);
            v = *(const float2*)(wr0 + ks * 16 + 2 * tg + 8); A[ks][2] = pack_f16x2(v.x, v.y);
            v = *(const float2*)(wr1 + ks * 16 + 2 * tg + 8); A[ks][3] = pack_f16x2(v.x, v.y);
        }

#pragma unroll
        for (int nt = 0; nt < 8; ++nt) {
            float acc[4] = {0.f, 0.f, 0.f, 0.f};
            mma16816(acc, A[0], B[nt][0][0], B[nt][0][1]);
            mma16816(acc, A[1], B[nt][1][0], B[nt][1][1]);
            const int b0 = nt * 8 + 2 * tg;
            *(__half2*)(ubase + (size_t)co0 * NB + b0) =
                __floats2half2_rn(acc[0], acc[1]);
            *(__half2*)(ubase + (size_t)(co0 + 8) * NB + b0) =
                __floats2half2_rn(acc[2], acc[3]);
        }
    }
}

// ---------------------------------------------------------------------------
// c_ij[c][:] = softmax over r of b[c][:]. One block per capsule c; contiguous.
__global__ void __launch_bounds__(256) k_softmax() {
    const int c   = blockIdx.x;
    const int tid = threadIdx.x;
    __shared__ float sm[8];
    const float* bp = g_blog + c * NR;

    float vals[8];
#pragma unroll
    for (int j = 0; j < 8; ++j) vals[j] = bp[tid + j * 256];

    float m = vals[0];
#pragma unroll
    for (int j = 1; j < 8; ++j) m = fmaxf(m, vals[j]);
#pragma unroll
    for (int off = 16; off; off >>= 1) m = fmaxf(m, __shfl_xor_sync(0xffffffffu, m, off));
    if ((tid & 31) == 0) sm[tid >> 5] = m;
    __syncthreads();
    float mm = sm[0];
#pragma unroll
    for (int j = 1; j < 8; ++j) mm = fmaxf(mm, sm[j]);
    __syncthreads();

    float e[8];
    float s = 0.f;
#pragma unroll
    for (int j = 0; j < 8; ++j) { e[j] = expf(vals[j] - mm); s += e[j]; }
#pragma unroll
    for (int off = 16; off; off >>= 1) s += __shfl_xor_sync(0xffffffffu, s, off);
    if ((tid & 31) == 0) sm[tid >> 5] = s;
    __syncthreads();
    float tot = 0.f;
#pragma unroll
    for (int j = 0; j < 8; ++j) tot += sm[j];
    const float inv = 1.f / tot;
    float* cp = g_cij + c * NR;
#pragma unroll
    for (int j = 0; j < 8; ++j) cp[tid + j * 256] = e[j] * inv;
}

// ---------------------------------------------------------------------------
// s partial: block (co2, q) covers routes [q*512, +512).
// warp = seg of 64 routes; lane: co_l = lane>>4, b-quad = (lane&15)*4.
// uniform=1: c_ij == 1/2048 exactly (iteration 0), skip the c load.
__global__ void __launch_bounds__(256) k_s(int uniform) {
    const int co2 = blockIdx.x;          // 0..511 (co pair)
    const int q   = blockIdx.y;          // 0..3 (route quarter)
    const int c   = co2 >> 4;
    const int tid = threadIdx.x;
    __shared__ float cs[512];
    __shared__ float red[8][128];

    if (!uniform) {
#pragma unroll
        for (int j = 0; j < 2; ++j)
            cs[tid + j * 256] = g_cij[c * NR + q * 512 + tid + j * 256];
        __syncthreads();
    }

    const int seg  = tid >> 5;
    const int lane = tid & 31;
    const int co_l = lane >> 4;
    const int b4   = (lane & 15) * 4;
    const int r0   = q * 512 + seg * 64;
    const uint2* p = (const uint2*)(g_uhat + (size_t)r0 * RSTRIDE
                                    + (size_t)co2 * 128 + co_l * 64 + b4);
    const float* csp = cs + seg * 64;

    float a0 = 0.f, a1 = 0.f, a2 = 0.f, a3 = 0.f;
#pragma unroll 8
    for (int k = 0; k < 64; ++k) {
        const uint2 u = __ldcs(&p[(size_t)k * (RSTRIDE / 4)]);
        const float2 f0 = __half22float2(*(const __half2*)&u.x);
        const float2 f1 = __half22float2(*(const __half2*)&u.y);
        const float cc = uniform ? C_UNI : csp[k];
        a0 = fmaf(cc, f0.x, a0);
        a1 = fmaf(cc, f0.y, a1);
        a2 = fmaf(cc, f1.x, a2);
        a3 = fmaf(cc, f1.y, a3);
    }
    red[seg][co_l * 64 + b4 + 0] = a0;
    red[seg][co_l * 64 + b4 + 1] = a1;
    red[seg][co_l * 64 + b4 + 2] = a2;
    red[seg][co_l * 64 + b4 + 3] = a3;
    __syncthreads();

    if (tid < 128) {
        float s = 0.f;
#pragma unroll
        for (int j = 0; j < 8; ++j) s += red[j][tid];
        g_spart[(co2 * 4 + q) * 128 + tid] = s;
    }
}

// ---------------------------------------------------------------------------
// Combine quarters, squash -> g_v2 (+ final output on last iter). 65536 lanes.
__global__ void __launch_bounds__(256) k_red(float* __restrict__ outp) {
    const int idx = blockIdx.x * 256 + threadIdx.x;   // co2*128 + e  (65536)
    const int co2 = idx >> 7, e = idx & 127;
    const float* pp = g_spart + co2 * 4 * 128 + e;
    const float s = (pp[0] + pp[128]) + (pp[256] + pp[384]);
    const int co = co2 * 2 + (e >> 6);
    const int b  = e & 63;
    const float sq = s * s;
    const float v  = sq * s / ((1.f + sq) * sqrtf(sq));
    g_v2[co * NB + b] = v;                 // [c][o][b] for the a-pass
    if (outp) outp[b * NCO + co] = v;      // [b][c][o][1] final output
}

// ---------------------------------------------------------------------------
// b[c][r] (+)= (1/B) * sum_{b,o} u_hat[r][c][o][b] * v[c][o][b].
// first=1: overwrite (replaces zero-init + first accumulate).
__global__ void __launch_bounds__(256) k_a(int first) {
    const int c    = blockIdx.y;
    const int r0   = blockIdx.x * 32;
    const int tid  = threadIdx.x;
    const int lane = tid & 31;
    const int w    = tid >> 5;
    __shared__ __align__(16) float vsm[NO * NB];  // 8 KB

    const float4* vsrc = (const float4*)(g_v2 + c * (NO * NB));
    float4* vdst = (float4*)vsm;
#pragma unroll
    for (int j = 0; j < 2; ++j) vdst[tid + j * 256] = vsrc[tid + j * 256];
    __syncthreads();

    float4 vr[16];
#pragma unroll
    for (int k = 0; k < 8; ++k) {
        vr[2 * k]     = ((const float4*)vsm)[2 * (lane + k * 32)];
        vr[2 * k + 1] = ((const float4*)vsm)[2 * (lane + k * 32) + 1];
    }

#pragma unroll
    for (int i = 0; i < 4; ++i) {
        const int r = r0 + w * 4 + i;
        const uint4* up = (const uint4*)(g_uhat + (size_t)r * RSTRIDE + c * (NO * NB));
        float p = 0.f;
#pragma unroll
        for (int k = 0; k < 8; ++k) {
            const uint4 u = __ldcs(&up[lane + k * 32]);
            const float2 f0 = __half22float2(*(const __half2*)&u.x);
            const float2 f1 = __half22float2(*(const __half2*)&u.y);
            const float2 f2 = __half22float2(*(const __half2*)&u.z);
            const float2 f3 = __half22float2(*(const __half2*)&u.w);
            const float4 v0 = vr[2 * k];
            const float4 v1 = vr[2 * k + 1];
            p = fmaf(f0.x, v0.x, p); p = fmaf(f0.y, v0.y, p);
            p = fmaf(f1.x, v0.z, p); p = fmaf(f1.y, v0.w, p);
            p = fmaf(f2.x, v1.x, p); p = fmaf(f2.y, v1.y, p);
            p = fmaf(f3.x, v1.z, p); p = fmaf(f3.y, v1.w, p);
        }
#pragma unroll
        for (int off = 16; off; off >>= 1) p += __shfl_xor_sync(0xffffffffu, p, off);
        if (lane == 0) {
            const float val = p * (1.f / NB);
            if (first) g_blog[c * NR + r] = val;
            else       g_blog[c * NR + r] += val;
        }
    }
}

// ---------------------------------------------------------------------------
extern "C" void kernel_launch(void* const* d_in, const int* in_sizes, int n_in,
                              void* d_out, int out_size) {
    const float* x = (const float*)d_in[0];  // [B, R, I]
    const float* W = (const float*)d_in[1];  // [R, C, O, I]
    if (n_in >= 2 && in_sizes[0] > in_sizes[1]) {  // robust to input ordering
        const float* t = x; x = W; W = t;
    }
    float* out = (float*)d_out;

    k_uhat<<<NR, 256>>>(x, W);

    // iteration 0: softmax(0) == exactly 1/2048 — skip zero + softmax
    k_s<<<dim3(512, 4), 256>>>(1);
    k_red<<<256, 256>>>(nullptr);
    k_a<<<dim3(64, 32), 256>>>(1);

    // iteration 1
    k_softmax<<<NC, 256>>>();
    k_s<<<dim3(512, 4), 256>>>(0);
    k_red<<<256, 256>>>(nullptr);
    k_a<<<dim3(64, 32), 256>>>(0);

    // iteration 2 (final)
    k_softmax<<<NC, 256>>>();
    k_s<<<dim3(512, 4), 256>>>(0);
    k_red<<<256, 256>>>(out);
}

// round 10
// speedup vs baseline: 1.2778x; 1.0355x over previous
#include <cuda_runtime.h>
#include <cuda_fp16.h>
#include <cstdint>
#include <cstddef>

#define NR 2048
#define NC 32
#define NO 32
#define NI 32
#define NB 64
#define NCO (NC*NO)        // 1024
#define RSTRIDE (NCO*NB)   // 65536 elements per route in u_hat
#define C_UNI (1.0f/2048.0f)

// Scratch (device globals: allocation-free contract)
__device__ __half g_uhat[(size_t)NR * NCO * NB]; // [r][c][o][b]  268 MB fp16
__device__ float  g_spart[512 * 4 * 128];        // k_s partials [co2][q][128]
__device__ float  g_blog[NC * NR];               // routing logits b_ij [c][r]
__device__ float  g_cij[NC * NR];                // softmax(b) over r, [c][r]
__device__ float  g_v2[NCO * NB];                // v in [c][o][b] layout

// ---------------------------------------------------------------------------
__device__ __forceinline__ uint32_t pack_f16x2(float a, float b) {
    uint32_t r;
    asm("cvt.rn.f16x2.f32 %0, %1, %2;" : "=r"(r) : "f"(b), "f"(a));
    return r;
}
// D += A*B (m16n8k16, fp16 in, fp32 acc) — plain mma.sync
__device__ __forceinline__ void mma16816(float* c, const uint32_t* a,
                                         uint32_t b0, uint32_t b1) {
    asm volatile(
        "mma.sync.aligned.m16n8k16.row.col.f32.f16.f16.f32 "
        "{%0,%1,%2,%3},{%4,%5,%6,%7},{%8,%9},{%0,%1,%2,%3};"
        : "+f"(c[0]), "+f"(c[1]), "+f"(c[2]), "+f"(c[3])
        : "r"(a[0]), "r"(a[1]), "r"(a[2]), "r"(a[3]), "r"(b0), "r"(b1));
}

// ---------------------------------------------------------------------------
// u_hat via mma.sync: per route r, D[1024co x 64b] = W_r[1024x32] @ x_r^T.
__global__ void __launch_bounds__(256) k_uhat(const float* __restrict__ x,
                                              const float* __restrict__ W) {
    const int r    = blockIdx.x;
    const int tid  = threadIdx.x;
    const int w    = tid >> 5;
    const int lane = tid & 31;
    const int g    = lane >> 2;
    const int tg   = lane & 3;

    uint32_t B[8][2][2];
#pragma unroll
    for (int nt = 0; nt < 8; ++nt) {
        const float* xr = x + (size_t)(nt * 8 + g) * (NR * NI) + (size_t)r * NI;
#pragma unroll
        for (int ks = 0; ks < 2; ++ks) {
            const float2 v0 = *(const float2*)(xr + ks * 16 + 2 * tg);
            const float2 v1 = *(const float2*)(xr + ks * 16 + 2 * tg + 8);
            B[nt][ks][0] = pack_f16x2(v0.x, v0.y);
            B[nt][ks][1] = pack_f16x2(v1.x, v1.y);
        }
    }

    const float* wbase = W + (size_t)r * (NCO * NI);
    __half* const ubase = g_uhat + (size_t)r * RSTRIDE;

#pragma unroll 1
    for (int mt = 0; mt < 8; ++mt) {
        const int co0 = w * 128 + mt * 16 + g;
        const float* wr0 = wbase + (size_t)co0 * NI;
        const float* wr1 = wr0 + 8 * NI;

        uint32_t A[2][4];
#pragma unroll
        for (int ks = 0; ks < 2; ++ks) {
            float2 v;
            v = *(const float2*)(wr0 + ks * 16 + 2 * tg);     A[ks][0] = pack_f16x2(v.x, v.y);
            v = *(const float2*)(wr1 + ks * 16 + 2 * tg);     A[ks][1] = pack_f16x2(v.x, v.y);
            v = *(const float2*)(wr0 + ks * 16 + 2 * tg + 8); A[ks][2] = pack_f16x2(v.x, v.y);
            v = *(const float2*)(wr1 + ks * 16 + 2 * tg + 8); A[ks][3] = pack_f16x2(v.x, v.y);
        }

#pragma unroll
        for (int nt = 0; nt < 8; ++nt) {
            float acc[4] = {0.f, 0.f, 0.f, 0.f};
            mma16816(acc, A[0], B[nt][0][0], B[nt][0][1]);
            mma16816(acc, A[1], B[nt][1][0], B[nt][1][1]);
            const int b0 = nt * 8 + 2 * tg;
            *(__half2*)(ubase + (size_t)co0 * NB + b0) =
                __floats2half2_rn(acc[0], acc[1]);
            *(__half2*)(ubase + (size_t)(co0 + 8) * NB + b0) =
                __floats2half2_rn(acc[2], acc[3]);
        }
    }
}

// ---------------------------------------------------------------------------
// c_ij[c][:] = softmax over r of b[c][:]. One block per capsule c; contiguous.
__global__ void __launch_bounds__(256) k_softmax() {
    const int c   = blockIdx.x;
    const int tid = threadIdx.x;
    __shared__ float sm[8];
    const float* bp = g_blog + c * NR;

    float vals[8];
#pragma unroll
    for (int j = 0; j < 8; ++j) vals[j] = bp[tid + j * 256];

    float m = vals[0];
#pragma unroll
    for (int j = 1; j < 8; ++j) m = fmaxf(m, vals[j]);
#pragma unroll
    for (int off = 16; off; off >>= 1) m = fmaxf(m, __shfl_xor_sync(0xffffffffu, m, off));
    if ((tid & 31) == 0) sm[tid >> 5] = m;
    __syncthreads();
    float mm = sm[0];
#pragma unroll
    for (int j = 1; j < 8; ++j) mm = fmaxf(mm, sm[j]);
    __syncthreads();

    float e[8];
    float s = 0.f;
#pragma unroll
    for (int j = 0; j < 8; ++j) { e[j] = expf(vals[j] - mm); s += e[j]; }
#pragma unroll
    for (int off = 16; off; off >>= 1) s += __shfl_xor_sync(0xffffffffu, s, off);
    if ((tid & 31) == 0) sm[tid >> 5] = s;
    __syncthreads();
    float tot = 0.f;
#pragma unroll
    for (int j = 0; j < 8; ++j) tot += sm[j];
    const float inv = 1.f / tot;
    float* cp = g_cij + c * NR;
#pragma unroll
    for (int j = 0; j < 8; ++j) cp[tid + j * 256] = e[j] * inv;
}

// ---------------------------------------------------------------------------
// s partial: block (co2, q) covers routes [q*512, +512).
__global__ void __launch_bounds__(256) k_s(int uniform) {
    const int co2 = blockIdx.x;
    const int q   = blockIdx.y;
    const int c   = co2 >> 4;
    const int tid = threadIdx.x;
    __shared__ float cs[512];
    __shared__ float red[8][128];

    if (!uniform) {
#pragma unroll
        for (int j = 0; j < 2; ++j)
            cs[tid + j * 256] = g_cij[c * NR + q * 512 + tid + j * 256];
        __syncthreads();
    }

    const int seg  = tid >> 5;
    const int lane = tid & 31;
    const int co_l = lane >> 4;
    const int b4   = (lane & 15) * 4;
    const int r0   = q * 512 + seg * 64;
    const uint2* p = (const uint2*)(g_uhat + (size_t)r0 * RSTRIDE
                                    + (size_t)co2 * 128 + co_l * 64 + b4);
    const float* csp = cs + seg * 64;

    float a0 = 0.f, a1 = 0.f, a2 = 0.f, a3 = 0.f;
#pragma unroll 16
    for (int k = 0; k < 64; ++k) {
        const uint2 u = __ldcs(&p[(size_t)k * (RSTRIDE / 4)]);
        const float2 f0 = __half22float2(*(const __half2*)&u.x);
        const float2 f1 = __half22float2(*(const __half2*)&u.y);
        const float cc = uniform ? C_UNI : csp[k];
        a0 = fmaf(cc, f0.x, a0);
        a1 = fmaf(cc, f0.y, a1);
        a2 = fmaf(cc, f1.x, a2);
        a3 = fmaf(cc, f1.y, a3);
    }
    red[seg][co_l * 64 + b4 + 0] = a0;
    red[seg][co_l * 64 + b4 + 1] = a1;
    red[seg][co_l * 64 + b4 + 2] = a2;
    red[seg][co_l * 64 + b4 + 3] = a3;
    __syncthreads();

    if (tid < 128) {
        float s = 0.f;
#pragma unroll
        for (int j = 0; j < 8; ++j) s += red[j][tid];
        g_spart[(co2 * 4 + q) * 128 + tid] = s;
    }
}

// ---------------------------------------------------------------------------
// Combine quarters, squash -> g_v2 (+ final output on last iter).
__global__ void __launch_bounds__(256) k_red(float* __restrict__ outp) {
    const int idx = blockIdx.x * 256 + threadIdx.x;
    const int co2 = idx >> 7, e = idx & 127;
    const float* pp = g_spart + co2 * 4 * 128 + e;
    const float s = (pp[0] + pp[128]) + (pp[256] + pp[384]);
    const int co = co2 * 2 + (e >> 6);
    const int b  = e & 63;
    const float sq = s * s;
    const float v  = sq * s / ((1.f + sq) * sqrtf(sq));
    g_v2[co * NB + b] = v;
    if (outp) outp[b * NCO + co] = v;
}

// ---------------------------------------------------------------------------
// b[c][r] (+)= (1/B) * sum_{b,o} u_hat[r][c][o][b] * v[c][o][b].
// Warp = (route-group rg of 16 routes, o-QUARTER oq). 4 o-quarters x 64 slots
// cover all 256 uint4 slots of each (r,c) row. Per lane: vr[4] float4 v-cache
// (16 regs), 2 uint4 u-loads per route; per-route dot via shuffle + smem atomic.
__global__ void __launch_bounds__(256) k_a(int first) {
    const int c    = blockIdx.y;
    const int r0   = blockIdx.x * 32;
    const int tid  = threadIdx.x;
    const int lane = tid & 31;
    const int w    = tid >> 5;
    const int oq   = w & 3;     // o-quarter: uint4 slots [oq*64, +64)
    const int rg   = w >> 2;    // route group of 16
    __shared__ __align__(16) float vsm[NO * NB];  // 8 KB
    __shared__ float a_sm[32];

    const float4* vsrc = (const float4*)(g_v2 + c * (NO * NB));
    float4* vdst = (float4*)vsm;
#pragma unroll
    for (int j = 0; j < 2; ++j) vdst[tid + j * 256] = vsrc[tid + j * 256];
    if (tid < 32) a_sm[tid] = 0.f;
    __syncthreads();

    // v for this lane's two uint4 slots s = oq*64 + k*32 + lane
    float4 vr[4];
#pragma unroll
    for (int k = 0; k < 2; ++k) {
        const int s = oq * 64 + k * 32 + lane;
        vr[2 * k]     = ((const float4*)vsm)[2 * s];
        vr[2 * k + 1] = ((const float4*)vsm)[2 * s + 1];
    }

#pragma unroll 4
    for (int it = 0; it < 16; ++it) {
        const int rl = rg * 16 + it;
        const int r  = r0 + rl;
        const uint4* up = (const uint4*)(g_uhat + (size_t)r * RSTRIDE
                                         + c * (NO * NB)) + oq * 64 + lane;
        const uint4 u0 = __ldcs(up);
        const uint4 u1 = __ldcs(up + 32);
        float p = 0.f;
        {
            const float2 f0 = __half22float2(*(const __half2*)&u0.x);
            const float2 f1 = __half22float2(*(const __half2*)&u0.y);
            const float2 f2 = __half22float2(*(const __half2*)&u0.z);
            const float2 f3 = __half22float2(*(const __half2*)&u0.w);
            p = fmaf(f0.x, vr[0].x, p); p = fmaf(f0.y, vr[0].y, p);
            p = fmaf(f1.x, vr[0].z, p); p = fmaf(f1.y, vr[0].w, p);
            p = fmaf(f2.x, vr[1].x, p); p = fmaf(f2.y, vr[1].y, p);
            p = fmaf(f3.x, vr[1].z, p); p = fmaf(f3.y, vr[1].w, p);
        }
        {
            const float2 f0 = __half22float2(*(const __half2*)&u1.x);
            const float2 f1 = __half22float2(*(const __half2*)&u1.y);
            const float2 f2 = __half22float2(*(const __half2*)&u1.z);
            const float2 f3 = __half22float2(*(const __half2*)&u1.w);
            p = fmaf(f0.x, vr[2].x, p); p = fmaf(f0.y, vr[2].y, p);
            p = fmaf(f1.x, vr[2].z, p); p = fmaf(f1.y, vr[2].w, p);
            p = fmaf(f2.x, vr[3].x, p); p = fmaf(f2.y, vr[3].y, p);
            p = fmaf(f3.x, vr[3].z, p); p = fmaf(f3.y, vr[3].w, p);
        }
#pragma unroll
        for (int off = 16; off; off >>= 1) p += __shfl_xor_sync(0xffffffffu, p, off);
        if (lane == 0) atomicAdd(&a_sm[rl], p);
    }
    __syncthreads();

    if (tid < 32) {
        const float val = a_sm[tid] * (1.f / NB);
        if (first) g_blog[c * NR + r0 + tid] = val;
        else       g_blog[c * NR + r0 + tid] += val;
    }
}

// ---------------------------------------------------------------------------
extern "C" void kernel_launch(void* const* d_in, const int* in_sizes, int n_in,
                              void* d_out, int out_size) {
    const float* x = (const float*)d_in[0];  // [B, R, I]
    const float* W = (const float*)d_in[1];  // [R, C, O, I]
    if (n_in >= 2 && in_sizes[0] > in_sizes[1]) {  // robust to input ordering
        const float* t = x; x = W; W = t;
    }
    float* out = (float*)d_out;

    k_uhat<<<NR, 256>>>(x, W);

    // iteration 0: softmax(0) == exactly 1/2048 — skip zero + softmax
    k_s<<<dim3(512, 4), 256>>>(1);
    k_red<<<256, 256>>>(nullptr);
    k_a<<<dim3(64, 32), 256>>>(1);

    // iteration 1
    k_softmax<<<NC, 256>>>();
    k_s<<<dim3(512, 4), 256>>>(0);
    k_red<<<256, 256>>>(nullptr);
    k_a<<<dim3(64, 32), 256>>>(0);

    // iteration 2 (final)
    k_softmax<<<NC, 256>>>();
    k_s<<<dim3(512, 4), 256>>>(0);
    k_red<<<256, 256>>>(out);
}